// round 2
// baseline (speedup 1.0000x reference)
#include <cuda_runtime.h>
#include <cstdint>

#define BB 16
#define AA 8400
#define GG 64
#define CC 80
#define KK 10
#define CAP 1024
#define FEPS 1e-9f

// Scratch (allocation-free rule: __device__ globals; zero-initialized at load).
// Invariant: every array is zero at kernel_launch entry; each call restores it.
__device__ unsigned long long g_key[BB * AA];    // packed (ciou_bits<<32)|(G-1-g)
__device__ unsigned int       g_normb[BB * AA];  // float bits of norm
__device__ int                g_maskbuf[BB * GG];
__device__ int                g_cnt[BB * GG];
__device__ unsigned long long g_ckey[BB * GG * CAP];  // (align_bits<<32)|(AA-a)
__device__ float              g_cov[BB * GG * CAP];   // ciou of candidate

// ---------------------------------------------------------------------------
// init: 1 block; decode gt_mask with runtime dtype detection
// ---------------------------------------------------------------------------
__global__ void init_kernel(const unsigned char* __restrict__ mask_raw) {
    __shared__ int s_f32, s_bf16, s_u8;
    if (threadIdx.x == 0) { s_f32 = 0; s_bf16 = 0; s_u8 = 0; }
    __syncthreads();
    for (int i = threadIdx.x; i < BB * GG; i += blockDim.x) {
        unsigned char byt = mask_raw[i];
        if (byt == 0x3F) {
            if ((i & 3) == 3) s_f32 = 1;
            if ((i & 3) == 1) s_bf16 = 1;
        }
        if (byt != 0 && (i & 3) != 0) s_u8 = 1;
    }
    __syncthreads();
    int mode = s_bf16 ? 3 : (s_f32 ? 2 : (s_u8 ? 0 : 1));
    for (int i = threadIdx.x; i < BB * GG; i += blockDim.x) {
        int v;
        if (mode == 0)      v = (mask_raw[i] != 0);
        else if (mode == 3) v = (((const unsigned short*)mask_raw)[i] != 0);
        else                v = (((const unsigned int*)mask_raw)[i] != 0);
        g_maskbuf[i] = v;
    }
}

// ---------------------------------------------------------------------------
// CIoU, mirroring reference op order; at1/at2 precomputed
// ---------------------------------------------------------------------------
__device__ __forceinline__ float ciou_fn(
    float gx1, float gy1, float gx2, float gy2,
    float area1, float at1,
    float dx1, float dy1, float dx2, float dy2,
    float w2, float h2, float at2)
{
    float xx1 = fmaxf(gx1, dx1), yy1 = fmaxf(gy1, dy1);
    float xx2 = fminf(gx2, dx2), yy2 = fminf(gy2, dy2);
    float iw = fmaxf(xx2 - xx1, 0.0f), ih = fmaxf(yy2 - yy1, 0.0f);
    float inter = iw * ih;
    float uni = area1 + w2 * h2 - inter;
    float iou = __fdiv_rn(inter, uni + FEPS);
    float cw = fmaxf(gx2, dx2) - fminf(gx1, dx1);
    float ch = fmaxf(gy2, dy2) - fminf(gy1, dy1);
    float c2 = cw * cw + ch * ch + FEPS;
    float ex = (gx1 + gx2) - (dx1 + dx2);
    float ey = (gy1 + gy2) - (dy1 + dy2);
    float rho2 = (ex * ex + ey * ey) * 0.25f;
    float dat = at1 - at2;
    float v = 0.40528473456935108577f * dat * dat;  // 4/pi^2
    float al = __fdiv_rn(v, v - iou + 1.0f + FEPS);
    return iou - (__fdiv_rn(rho2, c2) + v * al);
}

// ---------------------------------------------------------------------------
// scan: one thread per (b, anchor); GT boxes staged in shared.
// Pushes (align,a,ciou) candidates into per-(b,g) lists.
// ---------------------------------------------------------------------------
__global__ __launch_bounds__(256) void scan_kernel(
    const float* __restrict__ scores, const float* __restrict__ dbox,
    const float* __restrict__ anchors, const int* __restrict__ gt_labels,
    const float* __restrict__ gt_bboxes)
{
    int b = blockIdx.y;
    int a = blockIdx.x * 256 + threadIdx.x;

    __shared__ float s_gx1[GG], s_gy1[GG], s_gx2[GG], s_gy2[GG];
    __shared__ float s_area[GG], s_at1[GG];
    __shared__ int   s_lab[GG];

    if (threadIdx.x < GG) {
        int g = threadIdx.x, bg = b * GG + g;
        float4 gb = ((const float4*)gt_bboxes)[bg];
        s_gx1[g] = gb.x; s_gy1[g] = gb.y; s_gx2[g] = gb.z; s_gy2[g] = gb.w;
        float w1 = gb.z - gb.x, h1 = gb.w - gb.y;
        s_area[g] = w1 * h1;
        s_at1[g] = atanf(__fdiv_rn(w1, h1 + FEPS));
        int lab = gt_labels[bg];
        if (lab < 0) lab = 0;
        s_lab[g] = g_maskbuf[bg] ? lab : -1;
    }
    __syncthreads();
    if (a >= AA) return;

    float2 an = ((const float2*)anchors)[a];
    float4 d = ((const float4*)(dbox + (size_t)b * AA * 4))[a];
    float w2 = d.z - d.x, h2 = d.w - d.y;
    float at2 = atanf(__fdiv_rn(w2, h2 + FEPS));
    const float* srow = scores + ((size_t)b * AA + a) * CC;

#pragma unroll 4
    for (int g = 0; g < GG; g++) {
        int lab = s_lab[g];
        if (lab < 0) continue;
        if (!(s_gx1[g] < an.x && s_gy1[g] < an.y &&
              s_gx2[g] > an.x && s_gy2[g] > an.y)) continue;
        float ov = ciou_fn(s_gx1[g], s_gy1[g], s_gx2[g], s_gy2[g],
                           s_area[g], s_at1[g],
                           d.x, d.y, d.z, d.w, w2, h2, at2);
        if (ov <= 0.0f) continue;
        float s = __ldg(srow + lab);
        float p2 = ov * ov;
        float align = sqrtf(s) * (p2 * p2 * p2);
        if (align <= 0.0f) continue;
        int bg = b * GG + g;
        int pos = atomicAdd(&g_cnt[bg], 1);
        if (pos < CAP) {
            g_ckey[(size_t)bg * CAP + pos] =
                ((unsigned long long)__float_as_uint(align) << 32) |
                (unsigned int)(AA - a);  // smaller a -> larger key (tie-break)
            g_cov[(size_t)bg * CAP + pos] = ov;
        }
    }
}

// ---------------------------------------------------------------------------
// select: one warp per (b,g); top-10 over candidate list, no __syncthreads.
// Emits per-anchor argmax/norm atomics; resets g_cnt.
// ---------------------------------------------------------------------------
__global__ __launch_bounds__(256) void select_kernel(
    const float* __restrict__ dbox, const float* __restrict__ gt_bboxes)
{
    int bg = blockIdx.x * 8 + (threadIdx.x >> 5);
    int lane = threadIdx.x & 31;
    if (bg >= BB * GG) return;

    int n = g_cnt[bg];
    if (lane == 0) g_cnt[bg] = 0;
    if (n > CAP) n = CAP;
    if (n == 0) return;

    int b = bg / GG, g = bg % GG;

    // per-lane sorted top-10
    unsigned long long kk[KK];
#pragma unroll
    for (int j = 0; j < KK; j++) kk[j] = 0ull;
    const unsigned long long* ck = g_ckey + (size_t)bg * CAP;
    for (int i = lane; i < n; i += 32) {
        unsigned long long key = ck[i];
        if (key > kk[KK - 1]) {
            kk[KK - 1] = key;
#pragma unroll
            for (int j = KK - 2; j >= 0; j--) {
                unsigned long long x = kk[j], y = kk[j + 1];
                kk[j]     = x > y ? x : y;
                kk[j + 1] = x > y ? y : x;
            }
        }
    }

    // warp-wide strict-descending selection of top-10
    unsigned long long last = ~0ull;
    unsigned long long wkey = 0ull;  // this lane's winner (lane k holds round k)
    for (int k = 0; k < KK; k++) {
        unsigned long long cand = 0ull;
#pragma unroll
        for (int j = 0; j < KK; j++) {
            unsigned long long v = kk[j];
            if (v < last && v > cand) cand = v;
        }
#pragma unroll
        for (int o = 16; o; o >>= 1) {
            unsigned long long t = __shfl_xor_sync(0xffffffffu, cand, o);
            if (t > cand) cand = t;
        }
        if (lane == k) wkey = cand;
        last = cand;
        if (cand == 0ull) break;
    }

    // recompute ciou for winners (<=10), reduce max_ovl, emit atomics
    float my_ciou = 0.0f, my_align = 0.0f;
    int my_a = -1;
    if (lane < KK && wkey != 0ull) {
        my_a = AA - (int)(unsigned int)(wkey & 0xffffffffull);
        my_align = __uint_as_float((unsigned int)(wkey >> 32));
        float4 gb = ((const float4*)gt_bboxes)[bg];
        float w1 = gb.z - gb.x, h1 = gb.w - gb.y;
        float at1 = atanf(__fdiv_rn(w1, h1 + FEPS));
        float4 d = ((const float4*)(dbox + (size_t)b * AA * 4))[my_a];
        float w2 = d.z - d.x, h2 = d.w - d.y;
        float at2 = atanf(__fdiv_rn(w2, h2 + FEPS));
        my_ciou = ciou_fn(gb.x, gb.y, gb.z, gb.w, w1 * h1, at1,
                          d.x, d.y, d.z, d.w, w2, h2, at2);
    }
    float max_ovl = my_ciou;
#pragma unroll
    for (int o = 16; o; o >>= 1)
        max_ovl = fmaxf(max_ovl, __shfl_xor_sync(0xffffffffu, max_ovl, o));

    unsigned long long w0 = __shfl_sync(0xffffffffu, wkey, 0);
    float max_align = __uint_as_float((unsigned int)(w0 >> 32));

    if (my_a >= 0) {
        float normv = __fdiv_rn(my_align * max_ovl, max_align + FEPS);
        unsigned long long akey =
            ((unsigned long long)__float_as_uint(my_ciou) << 32) |
            (unsigned int)(GG - 1 - g);  // smaller g wins ties
        atomicMax(&g_key[(size_t)b * AA + my_a], akey);
        atomicMax(&g_normb[(size_t)b * AA + my_a], __float_as_uint(normv));
    }
}

// ---------------------------------------------------------------------------
// finalize: one warp per anchor; float4 stores; resets g_key/g_normb.
// Output layout: bbox[B,A,4] | cls_oh[B,A,C] | dist[B,A,1] | fg[B,A]
// ---------------------------------------------------------------------------
__global__ __launch_bounds__(256) void finalize_kernel(
    const int* __restrict__ gt_labels, const float* __restrict__ gt_bboxes,
    const float* __restrict__ gt_dist, float* __restrict__ out)
{
    int warp = blockIdx.x * 8 + (threadIdx.x >> 5);
    int lane = threadIdx.x & 31;
    if (warp >= BB * AA) return;
    int b = warp / AA;

    unsigned long long key = g_key[warp];
    float norm = __uint_as_float(g_normb[warp]);
    if (lane == 0) { g_key[warp] = 0ull; g_normb[warp] = 0u; }

    bool matched = (key != 0ull);
    int gm = matched ? (GG - 1 - (int)(unsigned int)(key & 0xffffffffull)) : 0;
    int base = b * GG + gm;

    float* out_bbox = out;
    float* out_cls  = out + (size_t)BB * AA * 4;
    float* out_dist = out_cls + (size_t)BB * AA * CC;
    float* out_fg   = out_dist + (size_t)BB * AA;

    if (lane < 20) {
        int label = matched ? __ldg(&gt_labels[base]) : -1;
        float4 v = make_float4(0.f, 0.f, 0.f, 0.f);
        if ((label >> 2) == lane) {
            int c = label & 3;
            if (c == 0) v.x = norm; else if (c == 1) v.y = norm;
            else if (c == 2) v.z = norm; else v.w = norm;
        }
        ((float4*)out_cls)[(size_t)warp * 20 + lane] = v;
    } else if (lane == 20) {
        float4 bb = matched ? ((const float4*)gt_bboxes)[base]
                            : make_float4(-1.f, -1.f, -1.f, -1.f);
        ((float4*)out_bbox)[warp] = bb;
    } else if (lane == 21) {
        out_dist[warp] = (matched ? __ldg(&gt_dist[base]) : -1.0f) * norm;
    } else if (lane == 22) {
        out_fg[warp] = 1.0f;  // argmax >= 0 always
    }
}

// ---------------------------------------------------------------------------
extern "C" void kernel_launch(void* const* d_in, const int* in_sizes, int n_in,
                              void* d_out, int out_size) {
    const float* scores = nullptr;
    const float* dbox = nullptr;
    const float* anchors = nullptr;
    const float* gtb = nullptr;
    const int* gtl = nullptr;
    const float* gtd = nullptr;
    const unsigned char* gmask = nullptr;
    int small_seen = 0;
    for (int i = 0; i < n_in; i++) {
        int s = in_sizes[i];
        if (s == BB * AA * CC)      scores = (const float*)d_in[i];
        else if (s == BB * AA * 4)  dbox = (const float*)d_in[i];
        else if (s == AA * 2)       anchors = (const float*)d_in[i];
        else if (s == BB * GG * 4)  gtb = (const float*)d_in[i];
        else if (s == BB * GG) {
            if (small_seen == 0)      gtl = (const int*)d_in[i];
            else if (small_seen == 1) gtd = (const float*)d_in[i];
            else                      gmask = (const unsigned char*)d_in[i];
            small_seen++;
        }
    }

    init_kernel<<<1, 256>>>(gmask);
    scan_kernel<<<dim3((AA + 255) / 256, BB), 256>>>(scores, dbox, anchors, gtl, gtb);
    select_kernel<<<(BB * GG + 7) / 8, 256>>>(dbox, gtb);
    finalize_kernel<<<(BB * AA + 7) / 8, 256>>>(gtl, gtb, gtd, (float*)d_out);
}

// round 3
// speedup vs baseline: 2.3900x; 2.3900x over previous
#include <cuda_runtime.h>
#include <cstdint>

#define BB 16
#define AA 8400
#define GG 64
#define CC 80
#define KK 10
#define CAP 1024
#define FEPS 1e-9f

// Scratch (allocation-free rule: __device__ globals; zero-initialized at load).
// Invariant: g_key/g_normb/g_cnt are zero at kernel_launch entry; each call
// restores the invariant (finalize resets key/norm, select resets cnt).
__device__ unsigned long long g_key[BB * AA];    // packed (ciou_bits<<32)|(G-1-g)
__device__ unsigned int       g_normb[BB * AA];  // float bits of norm
__device__ int                g_maskbuf[BB * GG];
__device__ int                g_cnt[BB * GG];
__device__ unsigned long long g_ckey[BB * GG * CAP];  // (align_bits<<32)|(AA-a)

// ---------------------------------------------------------------------------
// init: 1 block; decode gt_mask with runtime dtype detection
// ---------------------------------------------------------------------------
__global__ void init_kernel(const unsigned char* __restrict__ mask_raw) {
    __shared__ int s_f32, s_bf16, s_u8;
    if (threadIdx.x == 0) { s_f32 = 0; s_bf16 = 0; s_u8 = 0; }
    __syncthreads();
    for (int i = threadIdx.x; i < BB * GG; i += blockDim.x) {
        unsigned char byt = mask_raw[i];
        if (byt == 0x3F) {
            if ((i & 3) == 3) s_f32 = 1;
            if ((i & 3) == 1) s_bf16 = 1;
        }
        if (byt != 0 && (i & 3) != 0) s_u8 = 1;
    }
    __syncthreads();
    int mode = s_bf16 ? 3 : (s_f32 ? 2 : (s_u8 ? 0 : 1));
    for (int i = threadIdx.x; i < BB * GG; i += blockDim.x) {
        int v;
        if (mode == 0)      v = (mask_raw[i] != 0);
        else if (mode == 3) v = (((const unsigned short*)mask_raw)[i] != 0);
        else                v = (((const unsigned int*)mask_raw)[i] != 0);
        g_maskbuf[i] = v;
    }
}

// ---------------------------------------------------------------------------
// CIoU, mirroring reference op order; at1/at2 precomputed
// ---------------------------------------------------------------------------
__device__ __forceinline__ float ciou_fn(
    float gx1, float gy1, float gx2, float gy2,
    float area1, float at1,
    float dx1, float dy1, float dx2, float dy2,
    float w2, float h2, float at2)
{
    float xx1 = fmaxf(gx1, dx1), yy1 = fmaxf(gy1, dy1);
    float xx2 = fminf(gx2, dx2), yy2 = fminf(gy2, dy2);
    float iw = fmaxf(xx2 - xx1, 0.0f), ih = fmaxf(yy2 - yy1, 0.0f);
    float inter = iw * ih;
    float uni = area1 + w2 * h2 - inter;
    float iou = __fdiv_rn(inter, uni + FEPS);
    float cw = fmaxf(gx2, dx2) - fminf(gx1, dx1);
    float ch = fmaxf(gy2, dy2) - fminf(gy1, dy1);
    float c2 = cw * cw + ch * ch + FEPS;
    float ex = (gx1 + gx2) - (dx1 + dx2);
    float ey = (gy1 + gy2) - (dy1 + dy2);
    float rho2 = (ex * ex + ey * ey) * 0.25f;
    float dat = at1 - at2;
    float v = 0.40528473456935108577f * dat * dat;  // 4/pi^2
    float al = __fdiv_rn(v, v - iou + 1.0f + FEPS);
    return iou - (__fdiv_rn(rho2, c2) + v * al);
}

// ---------------------------------------------------------------------------
// scan: one thread per (b, anchor); GT boxes staged in shared as float4.
// Masked gts stored as empty boxes so the inside test rejects them.
// Survivors (~1%) push candidates into per-(b,g) lists.
// ---------------------------------------------------------------------------
__global__ __launch_bounds__(256) void scan_kernel(
    const float* __restrict__ scores, const float* __restrict__ dbox,
    const float* __restrict__ anchors, const int* __restrict__ gt_labels,
    const float* __restrict__ gt_bboxes)
{
    int b = blockIdx.y;
    int a = blockIdx.x * 256 + threadIdx.x;

    __shared__ float4 s_box[GG];                 // gt box (or empty if masked)
    __shared__ float  s_area[GG], s_at1[GG];
    __shared__ int    s_lab[GG];

    if (threadIdx.x < GG) {
        int g = threadIdx.x, bg = b * GG + g;
        float4 gb = ((const float4*)gt_bboxes)[bg];
        if (!g_maskbuf[bg]) gb = make_float4(1e30f, 1e30f, -1e30f, -1e30f);
        s_box[g] = gb;
        float w1 = gb.z - gb.x, h1 = gb.w - gb.y;
        s_area[g] = w1 * h1;
        s_at1[g] = atanf(__fdiv_rn(w1, h1 + FEPS));
        int lab = gt_labels[bg];
        s_lab[g] = lab < 0 ? 0 : lab;
    }
    __syncthreads();
    if (a >= AA) return;

    float2 an = ((const float2*)anchors)[a];
    float4 d = ((const float4*)(dbox + (size_t)b * AA * 4))[a];
    float w2 = d.z - d.x, h2 = d.w - d.y;
    float at2 = atanf(__fdiv_rn(w2, h2 + FEPS));
    const float* srow = scores + ((size_t)b * AA + a) * CC;

#pragma unroll 4
    for (int g = 0; g < GG; g++) {
        float4 gb = s_box[g];
        if (!(gb.x < an.x && gb.y < an.y && gb.z > an.x && gb.w > an.y))
            continue;
        float ov = ciou_fn(gb.x, gb.y, gb.z, gb.w, s_area[g], s_at1[g],
                           d.x, d.y, d.z, d.w, w2, h2, at2);
        if (ov <= 0.0f) continue;
        float s = __ldg(srow + s_lab[g]);
        float p2 = ov * ov;
        float align = sqrtf(s) * (p2 * p2 * p2);
        if (align <= 0.0f) continue;
        int bg = b * GG + g;
        int pos = atomicAdd(&g_cnt[bg], 1);
        if (pos < CAP) {
            g_ckey[(size_t)bg * CAP + pos] =
                ((unsigned long long)__float_as_uint(align) << 32) |
                (unsigned int)(AA - a);  // smaller a -> larger key (tie-break)
        }
    }
}

// ---------------------------------------------------------------------------
// select: one warp per (b,g); top-10 over candidate list, no __syncthreads.
// Emits per-anchor argmax/norm atomics; resets g_cnt.
// ---------------------------------------------------------------------------
__global__ __launch_bounds__(256) void select_kernel(
    const float* __restrict__ dbox, const float* __restrict__ gt_bboxes)
{
    int bg = blockIdx.x * 8 + (threadIdx.x >> 5);
    int lane = threadIdx.x & 31;
    if (bg >= BB * GG) return;

    int n = g_cnt[bg];
    if (lane == 0) g_cnt[bg] = 0;
    if (n > CAP) n = CAP;
    if (n == 0) return;

    int b = bg / GG, g = bg % GG;

    // per-lane sorted top-10
    unsigned long long kk[KK];
#pragma unroll
    for (int j = 0; j < KK; j++) kk[j] = 0ull;
    const unsigned long long* ck = g_ckey + (size_t)bg * CAP;
    for (int i = lane; i < n; i += 32) {
        unsigned long long key = ck[i];
        if (key > kk[KK - 1]) {
            kk[KK - 1] = key;
#pragma unroll
            for (int j = KK - 2; j >= 0; j--) {
                unsigned long long x = kk[j], y = kk[j + 1];
                kk[j]     = x > y ? x : y;
                kk[j + 1] = x > y ? y : x;
            }
        }
    }

    // warp-wide strict-descending selection of top-10
    unsigned long long last = ~0ull;
    unsigned long long wkey = 0ull;  // lane k holds round-k winner
    for (int k = 0; k < KK; k++) {
        unsigned long long cand = 0ull;
#pragma unroll
        for (int j = 0; j < KK; j++) {
            unsigned long long v = kk[j];
            if (v < last && v > cand) cand = v;
        }
#pragma unroll
        for (int o = 16; o; o >>= 1) {
            unsigned long long t = __shfl_xor_sync(0xffffffffu, cand, o);
            if (t > cand) cand = t;
        }
        if (lane == k) wkey = cand;
        last = cand;
        if (cand == 0ull) break;
    }

    // recompute ciou for winners (<=10), reduce max_ovl, emit atomics
    float my_ciou = 0.0f, my_align = 0.0f;
    int my_a = -1;
    if (lane < KK && wkey != 0ull) {
        my_a = AA - (int)(unsigned int)(wkey & 0xffffffffull);
        my_align = __uint_as_float((unsigned int)(wkey >> 32));
        float4 gb = ((const float4*)gt_bboxes)[bg];
        float w1 = gb.z - gb.x, h1 = gb.w - gb.y;
        float at1 = atanf(__fdiv_rn(w1, h1 + FEPS));
        float4 d = ((const float4*)(dbox + (size_t)b * AA * 4))[my_a];
        float w2 = d.z - d.x, h2 = d.w - d.y;
        float at2 = atanf(__fdiv_rn(w2, h2 + FEPS));
        my_ciou = ciou_fn(gb.x, gb.y, gb.z, gb.w, w1 * h1, at1,
                          d.x, d.y, d.z, d.w, w2, h2, at2);
    }
    float max_ovl = my_ciou;
#pragma unroll
    for (int o = 16; o; o >>= 1)
        max_ovl = fmaxf(max_ovl, __shfl_xor_sync(0xffffffffu, max_ovl, o));

    unsigned long long w0 = __shfl_sync(0xffffffffu, wkey, 0);
    float max_align = __uint_as_float((unsigned int)(w0 >> 32));

    if (my_a >= 0) {
        float normv = __fdiv_rn(my_align * max_ovl, max_align + FEPS);
        unsigned long long akey =
            ((unsigned long long)__float_as_uint(my_ciou) << 32) |
            (unsigned int)(GG - 1 - g);  // smaller g wins ties
        atomicMax(&g_key[(size_t)b * AA + my_a], akey);
        atomicMax(&g_normb[(size_t)b * AA + my_a], __float_as_uint(normv));
    }
}

// ---------------------------------------------------------------------------
// finalize: one block per 256 anchors. Phase 1: per-thread resolve into smem.
// Phase 2: dense coalesced float4 stores (no divergence, all lanes active).
// Output layout: bbox[B,A,4] | cls_oh[B,A,C] | dist[B,A,1] | fg[B,A]
// ---------------------------------------------------------------------------
__global__ __launch_bounds__(256) void finalize_kernel(
    const int* __restrict__ gt_labels, const float* __restrict__ gt_bboxes,
    const float* __restrict__ gt_dist, float* __restrict__ out)
{
    __shared__ int    s_label[256];
    __shared__ float  s_norm[256];
    __shared__ float4 s_bbox[256];
    __shared__ float  s_dist[256];

    int tid = threadIdx.x;
    int w = blockIdx.x * 256 + tid;     // global (b,a) index; grid covers exactly
    int b = w / AA;

    // Phase 1: resolve this anchor
    unsigned long long key = g_key[w];
    float norm = __uint_as_float(g_normb[w]);
    g_key[w] = 0ull;
    g_normb[w] = 0u;

    bool matched = (key != 0ull);
    int gm = matched ? (GG - 1 - (int)(unsigned int)(key & 0xffffffffull)) : 0;
    int base = b * GG + gm;

    s_label[tid] = matched ? __ldg(&gt_labels[base]) : -1;
    s_norm[tid]  = norm;
    s_bbox[tid]  = matched ? ((const float4*)gt_bboxes)[base]
                           : make_float4(-1.f, -1.f, -1.f, -1.f);
    s_dist[tid]  = (matched ? __ldg(&gt_dist[base]) : -1.0f) * norm;
    __syncthreads();

    float*  out_bbox = out;
    float4* out_cls4 = (float4*)(out + (size_t)BB * AA * 4);
    float*  out_dist = out + (size_t)BB * AA * (4 + CC);
    float*  out_fg   = out_dist + (size_t)BB * AA;

    // Phase 2a: class one-hot, 5120 consecutive float4s per block
    size_t cls_base = (size_t)blockIdx.x * 256 * (CC / 4);
#pragma unroll
    for (int rep = 0; rep < CC / 4; rep++) {
        int idx = rep * 256 + tid;           // [0, 5120)
        int la = idx / (CC / 4);             // local anchor
        int q  = idx % (CC / 4);             // float4 slot within the 80 classes
        int label = s_label[la];
        float4 v = make_float4(0.f, 0.f, 0.f, 0.f);
        if (label >= 0 && (label >> 2) == q) {
            float nv = s_norm[la];
            int c = label & 3;
            if (c == 0) v.x = nv; else if (c == 1) v.y = nv;
            else if (c == 2) v.z = nv; else v.w = nv;
        }
        out_cls4[cls_base + idx] = v;
    }

    // Phase 2b: bbox (one float4 per thread, coalesced)
    ((float4*)out_bbox)[w] = s_bbox[tid];

    // Phase 2c/d: dist and fg, vectorized
    if (tid < 64) {
        int t4 = tid * 4;
        ((float4*)out_dist)[blockIdx.x * 64 + tid] =
            make_float4(s_dist[t4], s_dist[t4 + 1], s_dist[t4 + 2], s_dist[t4 + 3]);
        ((float4*)out_fg)[blockIdx.x * 64 + tid] =
            make_float4(1.f, 1.f, 1.f, 1.f);   // argmax >= 0 always
    }
}

// ---------------------------------------------------------------------------
extern "C" void kernel_launch(void* const* d_in, const int* in_sizes, int n_in,
                              void* d_out, int out_size) {
    const float* scores = nullptr;
    const float* dbox = nullptr;
    const float* anchors = nullptr;
    const float* gtb = nullptr;
    const int* gtl = nullptr;
    const float* gtd = nullptr;
    const unsigned char* gmask = nullptr;
    int small_seen = 0;
    for (int i = 0; i < n_in; i++) {
        int s = in_sizes[i];
        if (s == BB * AA * CC)      scores = (const float*)d_in[i];
        else if (s == BB * AA * 4)  dbox = (const float*)d_in[i];
        else if (s == AA * 2)       anchors = (const float*)d_in[i];
        else if (s == BB * GG * 4)  gtb = (const float*)d_in[i];
        else if (s == BB * GG) {
            if (small_seen == 0)      gtl = (const int*)d_in[i];
            else if (small_seen == 1) gtd = (const float*)d_in[i];
            else                      gmask = (const unsigned char*)d_in[i];
            small_seen++;
        }
    }

    init_kernel<<<1, 256>>>(gmask);
    scan_kernel<<<dim3((AA + 255) / 256, BB), 256>>>(scores, dbox, anchors, gtl, gtb);
    select_kernel<<<(BB * GG + 7) / 8, 256>>>(dbox, gtb);
    finalize_kernel<<<BB * AA / 256, 256>>>(gtl, gtb, gtd, (float*)d_out);
}

// round 4
// speedup vs baseline: 2.5620x; 1.0720x over previous
#include <cuda_runtime.h>
#include <cstdint>

#define BB 16
#define AA 8400
#define GG 64
#define CC 80
#define KK 10
#define CAP 1024
#define FEPS 1e-9f

// Scratch (allocation-free rule: __device__ globals; zero-initialized at load).
// Invariant: g_key/g_normb/g_cnt are zero at kernel_launch entry; each call
// restores the invariant (finalize resets key/norm, select resets cnt).
__device__ unsigned long long g_key[BB * AA];    // packed (ciou_bits<<32)|(G-1-g)
__device__ unsigned int       g_normb[BB * AA];  // float bits of norm
__device__ int                g_cnt[BB * GG];
__device__ unsigned long long g_ckey[BB * GG * CAP];  // (align_bits<<32)|(AA-a)

// ---------------------------------------------------------------------------
// CIoU, mirroring reference op order; at1/at2 precomputed
// ---------------------------------------------------------------------------
__device__ __forceinline__ float ciou_fn(
    float gx1, float gy1, float gx2, float gy2,
    float area1, float at1,
    float dx1, float dy1, float dx2, float dy2,
    float w2, float h2, float at2)
{
    float xx1 = fmaxf(gx1, dx1), yy1 = fmaxf(gy1, dy1);
    float xx2 = fminf(gx2, dx2), yy2 = fminf(gy2, dy2);
    float iw = fmaxf(xx2 - xx1, 0.0f), ih = fmaxf(yy2 - yy1, 0.0f);
    float inter = iw * ih;
    float uni = area1 + w2 * h2 - inter;
    float iou = __fdiv_rn(inter, uni + FEPS);
    float cw = fmaxf(gx2, dx2) - fminf(gx1, dx1);
    float ch = fmaxf(gy2, dy2) - fminf(gy1, dy1);
    float c2 = cw * cw + ch * ch + FEPS;
    float ex = (gx1 + gx2) - (dx1 + dx2);
    float ey = (gy1 + gy2) - (dy1 + dy2);
    float rho2 = (ex * ex + ey * ey) * 0.25f;
    float dat = at1 - at2;
    float v = 0.40528473456935108577f * dat * dat;  // 4/pi^2
    float al = __fdiv_rn(v, v - iou + 1.0f + FEPS);
    return iou - (__fdiv_rn(rho2, c2) + v * al);
}

// ---------------------------------------------------------------------------
// scan: one thread per (b, anchor). Mask dtype detection + decode folded in.
// Block anchor-bbox pre-filter compacts the 64 GTs to the ~9 that can overlap
// this block's anchor stripe; main loop runs only over survivors.
// ---------------------------------------------------------------------------
__global__ __launch_bounds__(256) void scan_kernel(
    const float* __restrict__ scores, const float* __restrict__ dbox,
    const float* __restrict__ anchors, const int* __restrict__ gt_labels,
    const float* __restrict__ gt_bboxes, const unsigned char* __restrict__ mask_raw)
{
    int b = blockIdx.y;
    int tid = threadIdx.x;
    int a = blockIdx.x * 256 + tid;
    int ac = a < AA ? a : AA - 1;   // clamped for loads; duplicate anchor is
                                    // inside the block's range, harmless in bbox

    __shared__ float  s_part[8][4];     // per-warp {minx,miny,maxx,maxy}
    __shared__ float  s_bb[4];          // block bbox
    __shared__ float4 s_cbox[GG];       // compacted gt boxes
    __shared__ float4 s_caux[GG];       // {area1, at1, label, g}
    __shared__ int    s_m;

    float2 an = ((const float2*)anchors)[ac];

    // warp min/max of anchor coords
    float mnx = an.x, mny = an.y, mxx = an.x, mxy = an.y;
#pragma unroll
    for (int o = 16; o; o >>= 1) {
        mnx = fminf(mnx, __shfl_xor_sync(0xffffffffu, mnx, o));
        mny = fminf(mny, __shfl_xor_sync(0xffffffffu, mny, o));
        mxx = fmaxf(mxx, __shfl_xor_sync(0xffffffffu, mxx, o));
        mxy = fmaxf(mxy, __shfl_xor_sync(0xffffffffu, mxy, o));
    }
    int wid = tid >> 5, lane = tid & 31;
    if (lane == 0) {
        s_part[wid][0] = mnx; s_part[wid][1] = mny;
        s_part[wid][2] = mxx; s_part[wid][3] = mxy;
    }

    // mask dtype detection flags over first BB*GG bytes (in-bounds for all dtypes)
    unsigned int mword = ((const unsigned int*)mask_raw)[tid];  // 256 uints = 1024B
    int myflags = 0;
    if (((mword >> 24) & 0xFF) == 0x3F) myflags |= 1;            // f32 (byte 3)
    if (((mword >> 8)  & 0xFF) == 0x3F) myflags |= 2;            // bf16 (byte 1)
    if ((mword & 0xFFFFFF00u) != 0)     myflags |= 4;            // u8 packed
    int allflags = __syncthreads_or(myflags);                    // barrier 1

    if (tid == 0) {
        float bx = s_part[0][0], by = s_part[0][1];
        float cx = s_part[0][2], cy = s_part[0][3];
#pragma unroll
        for (int i = 1; i < 8; i++) {
            bx = fminf(bx, s_part[i][0]); by = fminf(by, s_part[i][1]);
            cx = fmaxf(cx, s_part[i][2]); cy = fmaxf(cy, s_part[i][3]);
        }
        s_bb[0] = bx; s_bb[1] = by; s_bb[2] = cx; s_bb[3] = cy;
    }
    __syncthreads();                                             // barrier 2

    // single warp: decode mask, test vs block bbox, ballot-compact
    if (tid < 32) {
        int mode = (allflags & 2) ? 3 : ((allflags & 1) ? 2 : ((allflags & 4) ? 0 : 1));
        float bminx = s_bb[0], bminy = s_bb[1], bmaxx = s_bb[2], bmaxy = s_bb[3];
        int base = 0;
#pragma unroll
        for (int half = 0; half < 2; half++) {
            int g = lane + half * 32;
            int bg = b * GG + g;
            int mk;
            if (mode == 0)      mk = (mask_raw[bg] != 0);
            else if (mode == 3) mk = (((const unsigned short*)mask_raw)[bg] != 0);
            else                mk = (((const unsigned int*)mask_raw)[bg] != 0);
            float4 gb = ((const float4*)gt_bboxes)[bg];
            bool pass = mk && gb.x < bmaxx && gb.z > bminx &&
                             gb.y < bmaxy && gb.w > bminy;
            unsigned int bal = __ballot_sync(0xffffffffu, pass);
            if (pass) {
                int pos = base + __popc(bal & ((1u << lane) - 1));
                s_cbox[pos] = gb;
                float w1 = gb.z - gb.x, h1 = gb.w - gb.y;
                int lab = gt_labels[bg];
                s_caux[pos] = make_float4(
                    w1 * h1, atanf(__fdiv_rn(w1, h1 + FEPS)),
                    __int_as_float(lab < 0 ? 0 : lab), __int_as_float(g));
            }
            base += __popc(bal);
        }
        if (lane == 0) s_m = base;
    }
    __syncthreads();                                             // barrier 3

    int m = s_m;
    if (a >= AA || m == 0) return;

    float4 d = ((const float4*)(dbox + (size_t)b * AA * 4))[a];
    float w2 = d.z - d.x, h2 = d.w - d.y;
    float at2 = atanf(__fdiv_rn(w2, h2 + FEPS));
    const float* srow = scores + ((size_t)b * AA + a) * CC;

    for (int j = 0; j < m; j++) {
        float4 gb = s_cbox[j];
        if (!(gb.x < an.x && gb.y < an.y && gb.z > an.x && gb.w > an.y))
            continue;
        float4 aux = s_caux[j];
        float ov = ciou_fn(gb.x, gb.y, gb.z, gb.w, aux.x, aux.y,
                           d.x, d.y, d.z, d.w, w2, h2, at2);
        if (ov <= 0.0f) continue;
        float s = __ldg(srow + __float_as_int(aux.z));
        float p2 = ov * ov;
        float align = sqrtf(s) * (p2 * p2 * p2);
        if (align <= 0.0f) continue;
        int bg = b * GG + __float_as_int(aux.w);
        int pos = atomicAdd(&g_cnt[bg], 1);
        if (pos < CAP) {
            g_ckey[(size_t)bg * CAP + pos] =
                ((unsigned long long)__float_as_uint(align) << 32) |
                (unsigned int)(AA - a);  // smaller a -> larger key (tie-break)
        }
    }
}

// ---------------------------------------------------------------------------
// select: one warp per (b,g); top-10 over candidate list, no __syncthreads.
// Emits per-anchor argmax/norm atomics; resets g_cnt.
// ---------------------------------------------------------------------------
__global__ __launch_bounds__(256) void select_kernel(
    const float* __restrict__ dbox, const float* __restrict__ gt_bboxes)
{
    int bg = blockIdx.x * 8 + (threadIdx.x >> 5);
    int lane = threadIdx.x & 31;
    if (bg >= BB * GG) return;

    int n = g_cnt[bg];
    if (lane == 0) g_cnt[bg] = 0;
    if (n > CAP) n = CAP;
    if (n == 0) return;

    int b = bg / GG, g = bg % GG;

    // per-lane sorted top-10
    unsigned long long kk[KK];
#pragma unroll
    for (int j = 0; j < KK; j++) kk[j] = 0ull;
    const unsigned long long* ck = g_ckey + (size_t)bg * CAP;
    for (int i = lane; i < n; i += 32) {
        unsigned long long key = ck[i];
        if (key > kk[KK - 1]) {
            kk[KK - 1] = key;
#pragma unroll
            for (int j = KK - 2; j >= 0; j--) {
                unsigned long long x = kk[j], y = kk[j + 1];
                kk[j]     = x > y ? x : y;
                kk[j + 1] = x > y ? y : x;
            }
        }
    }

    // warp-wide strict-descending selection of top-10
    unsigned long long last = ~0ull;
    unsigned long long wkey = 0ull;  // lane k holds round-k winner
    for (int k = 0; k < KK; k++) {
        unsigned long long cand = 0ull;
#pragma unroll
        for (int j = 0; j < KK; j++) {
            unsigned long long v = kk[j];
            if (v < last && v > cand) cand = v;
        }
#pragma unroll
        for (int o = 16; o; o >>= 1) {
            unsigned long long t = __shfl_xor_sync(0xffffffffu, cand, o);
            if (t > cand) cand = t;
        }
        if (lane == k) wkey = cand;
        last = cand;
        if (cand == 0ull) break;
    }

    // recompute ciou for winners (<=10), reduce max_ovl, emit atomics
    float my_ciou = 0.0f, my_align = 0.0f;
    int my_a = -1;
    if (lane < KK && wkey != 0ull) {
        my_a = AA - (int)(unsigned int)(wkey & 0xffffffffull);
        my_align = __uint_as_float((unsigned int)(wkey >> 32));
        float4 gb = ((const float4*)gt_bboxes)[bg];
        float w1 = gb.z - gb.x, h1 = gb.w - gb.y;
        float at1 = atanf(__fdiv_rn(w1, h1 + FEPS));
        float4 d = ((const float4*)(dbox + (size_t)b * AA * 4))[my_a];
        float w2 = d.z - d.x, h2 = d.w - d.y;
        float at2 = atanf(__fdiv_rn(w2, h2 + FEPS));
        my_ciou = ciou_fn(gb.x, gb.y, gb.z, gb.w, w1 * h1, at1,
                          d.x, d.y, d.z, d.w, w2, h2, at2);
    }
    float max_ovl = my_ciou;
#pragma unroll
    for (int o = 16; o; o >>= 1)
        max_ovl = fmaxf(max_ovl, __shfl_xor_sync(0xffffffffu, max_ovl, o));

    unsigned long long w0 = __shfl_sync(0xffffffffu, wkey, 0);
    float max_align = __uint_as_float((unsigned int)(w0 >> 32));

    if (my_a >= 0) {
        float normv = __fdiv_rn(my_align * max_ovl, max_align + FEPS);
        unsigned long long akey =
            ((unsigned long long)__float_as_uint(my_ciou) << 32) |
            (unsigned int)(GG - 1 - g);  // smaller g wins ties
        atomicMax(&g_key[(size_t)b * AA + my_a], akey);
        atomicMax(&g_normb[(size_t)b * AA + my_a], __float_as_uint(normv));
    }
}

// ---------------------------------------------------------------------------
// finalize: one thread per anchor, no smem. Zero-fill class region with
// unconditional STG.128, store bbox/dist/fg, then scatter norm into the
// one-hot slot (ordered by __syncthreads within the block that owns it).
// Output layout: bbox[B,A,4] | cls_oh[B,A,C] | dist[B,A,1] | fg[B,A]
// ---------------------------------------------------------------------------
__global__ __launch_bounds__(256) void finalize_kernel(
    const int* __restrict__ gt_labels, const float* __restrict__ gt_bboxes,
    const float* __restrict__ gt_dist, float* __restrict__ out)
{
    int tid = threadIdx.x;
    int w = blockIdx.x * 256 + tid;     // grid covers exactly BB*AA
    int b = w / AA;

    unsigned long long key = g_key[w];
    float norm = __uint_as_float(g_normb[w]);
    g_key[w] = 0ull;
    g_normb[w] = 0u;

    bool matched = (key != 0ull);
    int gm = matched ? (GG - 1 - (int)(unsigned int)(key & 0xffffffffull)) : 0;
    int base = b * GG + gm;

    int label = matched ? __ldg(&gt_labels[base]) : -1;
    float4 bb = matched ? ((const float4*)gt_bboxes)[base]
                        : make_float4(-1.f, -1.f, -1.f, -1.f);
    float dist = (matched ? __ldg(&gt_dist[base]) : -1.0f) * norm;

    float*  out_cls  = out + (size_t)BB * AA * 4;
    float4* out_cls4 = (float4*)out_cls;
    float*  out_dist = out + (size_t)BB * AA * (4 + CC);
    float*  out_fg   = out_dist + (size_t)BB * AA;

    // dense zero-fill of this block's class region (5120 float4s)
    size_t cls_base = (size_t)blockIdx.x * 256 * (CC / 4);
    float4 z = make_float4(0.f, 0.f, 0.f, 0.f);
#pragma unroll
    for (int rep = 0; rep < CC / 4; rep++)
        out_cls4[cls_base + rep * 256 + tid] = z;

    ((float4*)out)[w] = bb;
    out_dist[w] = dist;
    out_fg[w] = 1.0f;   // argmax >= 0 always

    __syncthreads();    // order zero-fill before scatter (same block owns region)
    if (matched && label >= 0 && label < CC)
        out_cls[(size_t)w * CC + label] = norm;
}

// ---------------------------------------------------------------------------
extern "C" void kernel_launch(void* const* d_in, const int* in_sizes, int n_in,
                              void* d_out, int out_size) {
    const float* scores = nullptr;
    const float* dbox = nullptr;
    const float* anchors = nullptr;
    const float* gtb = nullptr;
    const int* gtl = nullptr;
    const float* gtd = nullptr;
    const unsigned char* gmask = nullptr;
    int small_seen = 0;
    for (int i = 0; i < n_in; i++) {
        int s = in_sizes[i];
        if (s == BB * AA * CC)      scores = (const float*)d_in[i];
        else if (s == BB * AA * 4)  dbox = (const float*)d_in[i];
        else if (s == AA * 2)       anchors = (const float*)d_in[i];
        else if (s == BB * GG * 4)  gtb = (const float*)d_in[i];
        else if (s == BB * GG) {
            if (small_seen == 0)      gtl = (const int*)d_in[i];
            else if (small_seen == 1) gtd = (const float*)d_in[i];
            else                      gmask = (const unsigned char*)d_in[i];
            small_seen++;
        }
    }

    scan_kernel<<<dim3((AA + 255) / 256, BB), 256>>>(scores, dbox, anchors,
                                                     gtl, gtb, gmask);
    select_kernel<<<(BB * GG + 7) / 8, 256>>>(dbox, gtb);
    finalize_kernel<<<BB * AA / 256, 256>>>(gtl, gtb, gtd, (float*)d_out);
}